// round 7
// baseline (speedup 1.0000x reference)
#include <cuda_runtime.h>
#include <cstdint>
#include <math.h>

// Problem constants: B=1024, H=32, N=25, F=D=128
#define BH      32768
#define NK      26                  // self + neighbours (softmax length)
#define FDIM    128
#define DDIM    128
#define GRIDSZ  304                 // 2 blocks/SM x 152 SMs (GB300)
#define THREADS 256
#define NPAIR   3                   // pipeline depth in row-pairs
#define NSLOT   (2 * NPAIR)

#define ROW_FLOATS   (NK * FDIM)    // 3328 floats per staged row tile
#define SELF_BYTES   (FDIM * 4)     // 512
#define NEIGH_BYTES  (25 * FDIM * 4)// 12800
#define ROW_BYTES    (SELF_BYTES + NEIGH_BYTES) // 13312

typedef unsigned long long ull;

// ---------------------------------------------------------------------------
// TMA 1D bulk copy + mbarrier helpers
// ---------------------------------------------------------------------------
__device__ __forceinline__ void tma_bulk_1d(unsigned dst, const void* src,
                                            unsigned bytes, unsigned mbar) {
    asm volatile(
        "cp.async.bulk.shared::cluster.global.mbarrier::complete_tx::bytes "
        "[%0], [%1], %2, [%3];\n"
        :: "r"(dst), "l"(src), "r"(bytes), "r"(mbar) : "memory");
}
__device__ __forceinline__ void mbar_init(unsigned mbar, unsigned cnt) {
    asm volatile("mbarrier.init.shared.b64 [%0], %1;\n" :: "r"(mbar), "r"(cnt) : "memory");
}
__device__ __forceinline__ void mbar_expect_tx(unsigned mbar, unsigned bytes) {
    asm volatile("mbarrier.arrive.expect_tx.shared.b64 _, [%0], %1;\n"
                 :: "r"(mbar), "r"(bytes) : "memory");
}
__device__ __forceinline__ void mbar_wait(unsigned mbar, unsigned parity) {
    asm volatile(
        "{\n\t"
        ".reg .pred P;\n\t"
        "WL_%=:\n\t"
        "mbarrier.try_wait.parity.acquire.cta.shared::cta.b64 P, [%0], %1, 0x989680;\n\t"
        "@P bra WD_%=;\n\t"
        "bra WL_%=;\n\t"
        "WD_%=:\n\t"
        "}"
        :: "r"(mbar), "r"(parity) : "memory");
}

__global__ void __launch_bounds__(THREADS, 2)
fused_gat_kernel(const float* __restrict__ x_self,
                 const float* __restrict__ x_neigh,
                 const float* __restrict__ W,
                 const float* __restrict__ a_s,
                 const float* __restrict__ a_n,
                 float* __restrict__ out) {
    // slot layout: [0..127] = self row, [128..3327] = 25 neighbour rows
    __shared__ __align__(128) float xs[NSLOT][ROW_FLOATS];      // ~80 KB ring
    __shared__ __align__(16)  float wa_s_sm[FDIM];
    __shared__ __align__(16)  float wa_n_sm[FDIM];
    __shared__ float sc[2][32];                                  // raw scores A/B
    __shared__ __align__(16)  float xagg_sm[2][FDIM];
    __shared__ __align__(8)   ull  mbars[NPAIR];

    const int t    = threadIdx.x;
    const int warp = t >> 5;
    const int lane = t & 31;

    const unsigned xs_base  = (unsigned)__cvta_generic_to_shared(&xs[0][0]);
    const unsigned mbar_base = (unsigned)__cvta_generic_to_shared(&mbars[0]);

    // ---------------- mbarrier init + TMA pipeline prologue ----------------
    if (t == 0) {
#pragma unroll
        for (int i = 0; i < NPAIR; i++) mbar_init(mbar_base + 8 * i, 1);
        asm volatile("fence.proxy.async.shared::cta;\n" ::: "memory");
    }
    __syncthreads();

    const int G = GRIDSZ;
    // issue pair p: rows rA = bid + 2p*G, rB = rA + G into slots {2*(p%3), +1}
    auto issue_pair = [&](int p) {
        int rA = blockIdx.x + 2 * p * G;
        if (rA >= BH) return;
        int rB = rA + G;
        int nrows = (rB < BH) ? 2 : 1;
        unsigned mb = mbar_base + 8 * (p % NPAIR);
        unsigned s0 = xs_base + (unsigned)(2 * (p % NPAIR)) * (ROW_FLOATS * 4);
        mbar_expect_tx(mb, (unsigned)ROW_BYTES * nrows);
        tma_bulk_1d(s0,       x_self  + (size_t)rA * FDIM,        SELF_BYTES,  mb);
        tma_bulk_1d(s0 + SELF_BYTES, x_neigh + (size_t)rA * 25 * FDIM, NEIGH_BYTES, mb);
        if (nrows == 2) {
            unsigned s1 = s0 + ROW_FLOATS * 4;
            tma_bulk_1d(s1,       x_self  + (size_t)rB * FDIM,        SELF_BYTES,  mb);
            tma_bulk_1d(s1 + SELF_BYTES, x_neigh + (size_t)rB * 25 * FDIM, NEIGH_BYTES, mb);
        }
    };
    if (t == 0) {
        issue_pair(0); issue_pair(1); issue_pair(2);
    }

    // ---------------- prologue: wa = W @ a  (2 threads per f) ----------------
    {
        const int f  = t >> 1, hf = t & 1;
        const float* wr = W + (size_t)f * DDIM + hf * 64;
        const float* as = a_s + hf * 64;
        const float* an = a_n + hf * 64;
        float vs = 0.f, vn = 0.f;
#pragma unroll
        for (int j = 0; j < 64; j++) {
            float w = wr[j];
            vs = fmaf(w, as[j], vs);
            vn = fmaf(w, an[j], vn);
        }
        vs += __shfl_xor_sync(0xffffffffu, vs, 1);
        vn += __shfl_xor_sync(0xffffffffu, vn, 1);
        if (!hf) { wa_s_sm[f] = vs; wa_n_sm[f] = vn; }
    }

    // W register cache, packed f32x2 along f.
    // warp w covers d = w*16 + (lane&15); lanes 0-15: f-half 0, 16-31: f-half 1.
    const int h = lane >> 4;
    const int d = warp * 16 + (lane & 15);
    ull Wreg2[32];
#pragma unroll
    for (int i = 0; i < 32; i++) {
        int f = h * 64 + 2 * i;
        unsigned lo = __float_as_uint(W[(size_t)f * DDIM + d]);
        unsigned hi = __float_as_uint(W[(size_t)(f + 1) * DDIM + d]);
        Wreg2[i] = ((ull)hi << 32) | lo;
    }
    __syncthreads();     // wa_* visible

    // per-lane wa float4 slices (lane spans full 128 floats with 31 peers)
    const float4 wanL = reinterpret_cast<const float4*>(wa_n_sm)[lane];
    const float4 wasL = reinterpret_cast<const float4*>(wa_s_sm)[lane];

    // ---------------- main loop over row pairs ----------------
    int rowA = blockIdx.x;
    int p = 0;
    const int rsel = warp >> 2;        // warps 0-3 -> row A, 4-7 -> row B

    while (rowA < BH) {
        const int rowB = rowA + G;
        const bool bval = (rowB < BH);
        const int mb_i = p % NPAIR;

        mbar_wait(mbar_base + 8 * mb_i, (unsigned)((p / NPAIR) & 1));   // B1

        const float* slotA = &xs[2 * mb_i][0];
        const float* slotB = &xs[2 * mb_i + 1][0];

        // ---- scores: 54 dots, warp-per-dot, LDS.128 lane-consecutive ----
#pragma unroll
        for (int j = 0; j < 7; j++) {
            const int k = warp + 8 * j;
            if (k < 54) {
                const int sel = (k >= 27) ? 1 : 0;
                const int kk  = k - 27 * sel;
                if (!sel || bval) {
                    const float* sb = sel ? slotB : slotA;
                    // row kk at float offset kk*128 (kk==26 -> self row 0, wa_s)
                    const float4* xr = reinterpret_cast<const float4*>(
                        sb + ((kk == 26) ? 0 : kk) * FDIM);
                    float4 x4 = xr[lane];
                    float4 w4 = (kk == 26) ? wasL : wanL;
                    float v;
                    v =      x4.x * w4.x;
                    v = fmaf(x4.y, w4.y, v);
                    v = fmaf(x4.z, w4.z, v);
                    v = fmaf(x4.w, w4.w, v);
#pragma unroll
                    for (int o = 16; o; o >>= 1)
                        v += __shfl_xor_sync(0xffffffffu, v, o);
                    if (lane == 0) sc[sel][kk] = v;
                }
            }
        }
        __syncthreads();               // B2: scores visible

        // ---- softmax (redundant per warp) + xagg ----
        {
            float v  = (lane < 27) ? sc[rsel][lane] : 0.f;
            float ss = __shfl_sync(0xffffffffu, v, 26);
            float u  = (lane < NK) ? ss + v : -INFINITY;
            u = (u > 0.f) ? u : 0.2f * u;          // LeakyReLU(0.2)
            float m = u;
#pragma unroll
            for (int o = 16; o; o >>= 1) m = fmaxf(m, __shfl_xor_sync(0xffffffffu, m, o));
            float e  = (lane < NK) ? __expf(u - m) : 0.f;
            float smv = e;
#pragma unroll
            for (int o = 16; o; o >>= 1) smv += __shfl_xor_sync(0xffffffffu, smv, o);
            float pr = __fdividef(e, smv);

            if (!rsel || bval) {
                const int fidx = (warp & 3) * 32 + lane;
                const float* xc = (rsel ? slotB : slotA) + fidx;
                float acc = 0.f;
#pragma unroll
                for (int k = 0; k < NK; k++)
                    acc = fmaf(__shfl_sync(0xffffffffu, pr, k), xc[k * FDIM], acc);
                xagg_sm[rsel][fidx] = acc;
            }
        }
        __syncthreads();               // B3: xagg visible, xs reads complete

        // refill this ring slot for pair p+NPAIR (after B3: safe)
        if (t == 0) issue_pair(p + NPAIR);

        // ---- GEMV (both rows) from packed register W; LDS.128 broadcasts ----
#pragma unroll
        for (int r = 0; r < 2; r++) {
            if (r == 0 || bval) {
                ull a0 = 0, a1 = 0;
                const longlong2* xa =
                    reinterpret_cast<const longlong2*>(&xagg_sm[r][h * 64]);
#pragma unroll
                for (int i = 0; i < 16; i++) {
                    longlong2 q = xa[i];
                    asm volatile("fma.rn.f32x2 %0, %1, %2, %0;\n"
                                 : "+l"(a0) : "l"((ull)q.x), "l"(Wreg2[2 * i]));
                    asm volatile("fma.rn.f32x2 %0, %1, %2, %0;\n"
                                 : "+l"(a1) : "l"((ull)q.y), "l"(Wreg2[2 * i + 1]));
                }
                float o = __uint_as_float((unsigned)a0) +
                          __uint_as_float((unsigned)(a0 >> 32)) +
                          __uint_as_float((unsigned)a1) +
                          __uint_as_float((unsigned)(a1 >> 32));
                o += __shfl_xor_sync(0xffffffffu, o, 16);   // combine f-halves
                if (h == 0) {
                    int orow = rowA + r * G;
                    out[(size_t)orow * DDIM + d] = (o > 0.f) ? o : 0.f;
                }
            }
        }

        rowA += 2 * G;
        p++;
    }
}

// ---------------------------------------------------------------------------
extern "C" void kernel_launch(void* const* d_in, const int* in_sizes, int n_in,
                              void* d_out, int out_size) {
    const float* x_self  = (const float*)d_in[0];   // [1024,32,128]
    const float* x_neigh = (const float*)d_in[1];   // [1024,32,25,128]
    const float* w_feat  = (const float*)d_in[2];   // [128,128]
    const float* a_self  = (const float*)d_in[3];   // [128,1]
    const float* a_neigh = (const float*)d_in[4];   // [128,1]
    float*       out     = (float*)d_out;           // [1024,32,128]

    fused_gat_kernel<<<GRIDSZ, THREADS>>>(x_self, x_neigh, w_feat,
                                          a_self, a_neigh, out);
}

// round 8
// speedup vs baseline: 1.0465x; 1.0465x over previous
#include <cuda_runtime.h>
#include <cstdint>
#include <math.h>

// Problem constants: B=1024, H=32, N=25, F=D=128
#define BH      32768
#define NK      26                  // aggregation length (self + neighbours)
#define FDIM    128
#define DDIM    128
#define GRIDSZ  304                 // 2 blocks/SM x 152 SMs (GB300)
#define THREADS 256
#define NPAIR   3                   // pipeline depth in row-pairs
#define NSLOT   (2 * NPAIR)

#define ROW_FLOATS   (NK * FDIM)    // 3328 floats per staged row tile
#define SELF_BYTES   (FDIM * 4)     // 512
#define NEIGH_BYTES  (25 * FDIM * 4)// 12800
#define ROW_BYTES    (SELF_BYTES + NEIGH_BYTES) // 13312

typedef unsigned long long ull;

// ---------------------------------------------------------------------------
// TMA 1D bulk copy + mbarrier helpers
// ---------------------------------------------------------------------------
__device__ __forceinline__ void tma_bulk_1d(unsigned dst, const void* src,
                                            unsigned bytes, unsigned mbar) {
    asm volatile(
        "cp.async.bulk.shared::cluster.global.mbarrier::complete_tx::bytes "
        "[%0], [%1], %2, [%3];\n"
        :: "r"(dst), "l"(src), "r"(bytes), "r"(mbar) : "memory");
}
__device__ __forceinline__ void mbar_init(unsigned mbar, unsigned cnt) {
    asm volatile("mbarrier.init.shared.b64 [%0], %1;\n" :: "r"(mbar), "r"(cnt) : "memory");
}
__device__ __forceinline__ void mbar_expect_tx(unsigned mbar, unsigned bytes) {
    asm volatile("mbarrier.arrive.expect_tx.shared.b64 _, [%0], %1;\n"
                 :: "r"(mbar), "r"(bytes) : "memory");
}
__device__ __forceinline__ void mbar_wait(unsigned mbar, unsigned parity) {
    asm volatile(
        "{\n\t"
        ".reg .pred P;\n\t"
        "WL_%=:\n\t"
        "mbarrier.try_wait.parity.acquire.cta.shared::cta.b64 P, [%0], %1, 0x989680;\n\t"
        "@P bra WD_%=;\n\t"
        "bra WL_%=;\n\t"
        "WD_%=:\n\t"
        "}"
        :: "r"(mbar), "r"(parity) : "memory");
}

__global__ void __launch_bounds__(THREADS, 2)
fused_gat_kernel(const float* __restrict__ x_self,
                 const float* __restrict__ x_neigh,
                 const float* __restrict__ W,
                 const float* __restrict__ a_s,
                 const float* __restrict__ a_n,
                 float* __restrict__ out) {
    __shared__ __align__(128) float xs[NSLOT][ROW_FLOATS];      // ~80 KB ring
    __shared__ __align__(16)  float wa_s_sm[FDIM];
    __shared__ __align__(16)  float wa_n_sm[FDIM];
    __shared__ float sc[2][32];                                  // raw scores A/B
    __shared__ __align__(16)  float xpart[2][4][FDIM];           // per-warp partial agg
    __shared__ __align__(16)  float xagg_il[2][FDIM];            // interleaved for GEMV
    __shared__ __align__(8)   ull  mbars[NPAIR];

    const int t    = threadIdx.x;
    const int warp = t >> 5;
    const int lane = t & 31;

    const unsigned xs_base   = (unsigned)__cvta_generic_to_shared(&xs[0][0]);
    const unsigned mbar_base = (unsigned)__cvta_generic_to_shared(&mbars[0]);

    // ---------------- mbarrier init + TMA pipeline prologue ----------------
    if (t == 0) {
#pragma unroll
        for (int i = 0; i < NPAIR; i++) mbar_init(mbar_base + 8 * i, 1);
        asm volatile("fence.proxy.async.shared::cta;\n" ::: "memory");
    }
    __syncthreads();

    const int G = GRIDSZ;
    auto issue_pair = [&](int p) {
        int rA = blockIdx.x + 2 * p * G;
        if (rA >= BH) return;
        int rB = rA + G;
        int nrows = (rB < BH) ? 2 : 1;
        unsigned mb = mbar_base + 8 * (p % NPAIR);
        unsigned s0 = xs_base + (unsigned)(2 * (p % NPAIR)) * (ROW_FLOATS * 4);
        mbar_expect_tx(mb, (unsigned)ROW_BYTES * nrows);
        tma_bulk_1d(s0,              x_self  + (size_t)rA * FDIM,      SELF_BYTES,  mb);
        tma_bulk_1d(s0 + SELF_BYTES, x_neigh + (size_t)rA * 25 * FDIM, NEIGH_BYTES, mb);
        if (nrows == 2) {
            unsigned s1 = s0 + ROW_FLOATS * 4;
            tma_bulk_1d(s1,              x_self  + (size_t)rB * FDIM,      SELF_BYTES,  mb);
            tma_bulk_1d(s1 + SELF_BYTES, x_neigh + (size_t)rB * 25 * FDIM, NEIGH_BYTES, mb);
        }
    };
    if (t == 0) { issue_pair(0); issue_pair(1); issue_pair(2); }

    // ---------------- prologue: wa = W @ a  (2 threads per f) ----------------
    {
        const int f  = t >> 1, hf = t & 1;
        const float* wr = W + (size_t)f * DDIM + hf * 64;
        const float* as = a_s + hf * 64;
        const float* an = a_n + hf * 64;
        float vs = 0.f, vn = 0.f;
#pragma unroll
        for (int j = 0; j < 64; j++) {
            float w = wr[j];
            vs = fmaf(w, as[j], vs);
            vn = fmaf(w, an[j], vn);
        }
        vs += __shfl_xor_sync(0xffffffffu, vs, 1);
        vn += __shfl_xor_sync(0xffffffffu, vn, 1);
        if (!hf) { wa_s_sm[f] = vs; wa_n_sm[f] = vn; }
    }

    // W register cache, packed f32x2 along f.
    // warp w covers d = w*16 + (lane&15); lanes 0-15: f-half 0, 16-31: f-half 1.
    const int h = lane >> 4;
    const int d = warp * 16 + (lane & 15);
    ull Wreg2[32];
#pragma unroll
    for (int i = 0; i < 32; i++) {
        int f = h * 64 + 2 * i;
        unsigned lo = __float_as_uint(W[(size_t)f * DDIM + d]);
        unsigned hi = __float_as_uint(W[(size_t)(f + 1) * DDIM + d]);
        Wreg2[i] = ((ull)hi << 32) | lo;
    }
    __syncthreads();     // wa_* visible

    const float4 wanL = reinterpret_cast<const float4*>(wa_n_sm)[lane];
    const float4 wasL = reinterpret_cast<const float4*>(wa_s_sm)[lane];

    // ---------------- main loop over row pairs ----------------
    int rowA = blockIdx.x;
    int p = 0;
    const int rsel = warp >> 2;        // warps 0-3 -> row A, 4-7 -> row B
    const int w4   = warp & 3;

    while (rowA < BH) {
        const int  rowB = rowA + G;
        const bool bval = (rowB < BH);
        const bool mywork = (rsel == 0) || bval;
        const int  mb_i = p % NPAIR;

        mbar_wait(mbar_base + 8 * mb_i, (unsigned)((p / NPAIR) & 1));   // B1

        const float* slot = &xs[2 * mb_i + rsel][0];

        // ---- scores for OWN row: 7 dots/warp, k = w4 + 4j; keep x4 in regs ----
        float4 xk[7];
        if (mywork) {
#pragma unroll
            for (int j = 0; j < 7; j++) {
                const int k = w4 + 4 * j;
                if (k <= 26) {
                    const float4* xr = reinterpret_cast<const float4*>(
                        slot + ((k == 26) ? 0 : k) * FDIM);
                    float4 x4 = xr[lane];
                    xk[j] = x4;
                    float4 wv = (k == 26) ? wasL : wanL;
                    float v;
                    v =      x4.x * wv.x;
                    v = fmaf(x4.y, wv.y, v);
                    v = fmaf(x4.z, wv.z, v);
                    v = fmaf(x4.w, wv.w, v);
#pragma unroll
                    for (int o = 16; o; o >>= 1)
                        v += __shfl_xor_sync(0xffffffffu, v, o);
                    if (lane == 0) sc[rsel][k] = v;
                }
            }
        }
        __syncthreads();               // B2: scores visible; tile reads complete

        // tile slot is dead from here: refill early for DRAM overlap
        if (t == 0) issue_pair(p + NPAIR);

        // ---- softmax (own row, redundant per warp) + register aggregation ----
        if (mywork) {
            float v  = (lane < 27) ? sc[rsel][lane] : 0.f;
            float ss = __shfl_sync(0xffffffffu, v, 26);
            float u  = (lane < NK) ? ss + v : -INFINITY;
            u = (u > 0.f) ? u : 0.2f * u;          // LeakyReLU(0.2)
            float m = u;
#pragma unroll
            for (int o = 16; o; o >>= 1) m = fmaxf(m, __shfl_xor_sync(0xffffffffu, m, o));
            float e   = (lane < NK) ? __expf(u - m) : 0.f;
            float smv = e;
#pragma unroll
            for (int o = 16; o; o >>= 1) smv += __shfl_xor_sync(0xffffffffu, smv, o);
            float pr = __fdividef(e, smv);

            // partial xagg from registers: sum over this warp's k (< 26)
            float4 part = make_float4(0.f, 0.f, 0.f, 0.f);
#pragma unroll
            for (int j = 0; j < 7; j++) {
                const int k = w4 + 4 * j;
                if (k < NK) {
                    float pk = __shfl_sync(0xffffffffu, pr, k);
                    part.x = fmaf(pk, xk[j].x, part.x);
                    part.y = fmaf(pk, xk[j].y, part.y);
                    part.z = fmaf(pk, xk[j].z, part.z);
                    part.w = fmaf(pk, xk[j].w, part.w);
                }
            }
            reinterpret_cast<float4*>(&xpart[rsel][w4][0])[lane] = part;
        }
        __syncthreads();               // B3: partials visible

        // ---- reduce 4 partials -> interleaved xagg (one thread per (r,f)) ----
        {
            const int r = t >> 7, f = t & 127;
            if (r == 0 || bval) {
                float val = xpart[r][0][f] + xpart[r][1][f]
                          + xpart[r][2][f] + xpart[r][3][f];
                int s = (f < 64) ? (8 * (f >> 2) + (f & 3))
                                 : (8 * ((f - 64) >> 2) + 4 + (f & 3));
                xagg_il[r][s] = val;
            }
        }
        __syncthreads();               // B4: xagg visible

        // ---- GEMV (both rows) from packed register W; conflict-free LDS.128 ----
#pragma unroll
        for (int r = 0; r < 2; r++) {
            if (r == 0 || bval) {
                ull a0 = 0, a1 = 0;
#pragma unroll
                for (int i = 0; i < 16; i++) {
                    // h=0 reads bytes [32i,32i+16); h=1 reads [32i+16,32i+32)
                    longlong2 q = *reinterpret_cast<const longlong2*>(
                        &xagg_il[r][8 * i + 4 * h]);
                    asm volatile("fma.rn.f32x2 %0, %1, %2, %0;\n"
                                 : "+l"(a0) : "l"((ull)q.x), "l"(Wreg2[2 * i]));
                    asm volatile("fma.rn.f32x2 %0, %1, %2, %0;\n"
                                 : "+l"(a1) : "l"((ull)q.y), "l"(Wreg2[2 * i + 1]));
                }
                float o = __uint_as_float((unsigned)a0) +
                          __uint_as_float((unsigned)(a0 >> 32)) +
                          __uint_as_float((unsigned)a1) +
                          __uint_as_float((unsigned)(a1 >> 32));
                o += __shfl_xor_sync(0xffffffffu, o, 16);   // combine f-halves
                if (h == 0) {
                    int orow = rowA + r * G;
                    out[(size_t)orow * DDIM + d] = (o > 0.f) ? o : 0.f;
                }
            }
        }

        rowA += 2 * G;
        p++;
    }
}

// ---------------------------------------------------------------------------
extern "C" void kernel_launch(void* const* d_in, const int* in_sizes, int n_in,
                              void* d_out, int out_size) {
    const float* x_self  = (const float*)d_in[0];   // [1024,32,128]
    const float* x_neigh = (const float*)d_in[1];   // [1024,32,25,128]
    const float* w_feat  = (const float*)d_in[2];   // [128,128]
    const float* a_self  = (const float*)d_in[3];   // [128,1]
    const float* a_neigh = (const float*)d_in[4];   // [128,1]
    float*       out     = (float*)d_out;           // [1024,32,128]

    fused_gat_kernel<<<GRIDSZ, THREADS>>>(x_self, x_neigh, w_feat,
                                          a_self, a_neigh, out);
}

// round 9
// speedup vs baseline: 1.1717x; 1.1197x over previous
#include <cuda_runtime.h>
#include <cstdint>
#include <math.h>

// Problem constants: B=1024, H=32, N=25, F=D=128
#define BH      32768
#define NK      26                  // aggregation length (self + neighbours)
#define FDIM    128
#define DDIM    128
#define GRIDSZ  304                 // 2 blocks/SM x 152 SMs (GB300)
#define THREADS 256
#define NPAIR   3                   // TMA ring depth in row-pairs
#define NSLOT   (2 * NPAIR)

#define ROW_FLOATS   (NK * FDIM)    // 3328 floats per staged row tile
#define SELF_BYTES   (FDIM * 4)     // 512
#define NEIGH_BYTES  (25 * FDIM * 4)// 12800
#define ROW_BYTES    (SELF_BYTES + NEIGH_BYTES) // 13312

typedef unsigned long long ull;

// ---------------------------------------------------------------------------
// TMA 1D bulk copy + mbarrier helpers
// ---------------------------------------------------------------------------
__device__ __forceinline__ void tma_bulk_1d(unsigned dst, const void* src,
                                            unsigned bytes, unsigned mbar) {
    asm volatile(
        "cp.async.bulk.shared::cluster.global.mbarrier::complete_tx::bytes "
        "[%0], [%1], %2, [%3];\n"
        :: "r"(dst), "l"(src), "r"(bytes), "r"(mbar) : "memory");
}
__device__ __forceinline__ void mbar_init(unsigned mbar, unsigned cnt) {
    asm volatile("mbarrier.init.shared.b64 [%0], %1;\n" :: "r"(mbar), "r"(cnt) : "memory");
}
__device__ __forceinline__ void mbar_expect_tx(unsigned mbar, unsigned bytes) {
    asm volatile("mbarrier.arrive.expect_tx.shared.b64 _, [%0], %1;\n"
                 :: "r"(mbar), "r"(bytes) : "memory");
}
__device__ __forceinline__ void mbar_wait(unsigned mbar, unsigned parity) {
    asm volatile(
        "{\n\t"
        ".reg .pred P;\n\t"
        "WL_%=:\n\t"
        "mbarrier.try_wait.parity.acquire.cta.shared::cta.b64 P, [%0], %1, 0x989680;\n\t"
        "@P bra WD_%=;\n\t"
        "bra WL_%=;\n\t"
        "WD_%=:\n\t"
        "}"
        :: "r"(mbar), "r"(parity) : "memory");
}

__global__ void __launch_bounds__(THREADS, 2)
fused_gat_kernel(const float* __restrict__ x_self,
                 const float* __restrict__ x_neigh,
                 const float* __restrict__ W,
                 const float* __restrict__ a_s,
                 const float* __restrict__ a_n,
                 float* __restrict__ out) {
    __shared__ __align__(128) float xs[NSLOT][ROW_FLOATS];      // ~80 KB ring
    __shared__ __align__(16)  float wa_s_sm[FDIM];
    __shared__ __align__(16)  float wa_n_sm[FDIM];
    __shared__ float sc[4][32];                                  // raw scores, 4 rows
    __shared__ __align__(16)  float xpart[4][4][FDIM];           // per-warp partials
    __shared__ __align__(16)  float xagg_il[4][FDIM];            // interleaved for GEMV
    __shared__ __align__(8)   ull  mbars[NPAIR];

    const int t    = threadIdx.x;
    const int warp = t >> 5;
    const int lane = t & 31;

    const unsigned xs_base   = (unsigned)__cvta_generic_to_shared(&xs[0][0]);
    const unsigned mbar_base = (unsigned)__cvta_generic_to_shared(&mbars[0]);

    if (t == 0) {
#pragma unroll
        for (int i = 0; i < NPAIR; i++) mbar_init(mbar_base + 8 * i, 1);
        asm volatile("fence.proxy.async.shared::cta;\n" ::: "memory");
    }
    __syncthreads();

    const int G = GRIDSZ;
    auto issue_pair = [&](int p) {
        int rA = blockIdx.x + 2 * p * G;
        if (rA >= BH) return;
        int rB = rA + G;
        int nrows = (rB < BH) ? 2 : 1;
        unsigned mb = mbar_base + 8 * (p % NPAIR);
        unsigned s0 = xs_base + (unsigned)(2 * (p % NPAIR)) * (ROW_FLOATS * 4);
        mbar_expect_tx(mb, (unsigned)ROW_BYTES * nrows);
        tma_bulk_1d(s0,              x_self  + (size_t)rA * FDIM,      SELF_BYTES,  mb);
        tma_bulk_1d(s0 + SELF_BYTES, x_neigh + (size_t)rA * 25 * FDIM, NEIGH_BYTES, mb);
        if (nrows == 2) {
            unsigned s1 = s0 + ROW_FLOATS * 4;
            tma_bulk_1d(s1,              x_self  + (size_t)rB * FDIM,      SELF_BYTES,  mb);
            tma_bulk_1d(s1 + SELF_BYTES, x_neigh + (size_t)rB * 25 * FDIM, NEIGH_BYTES, mb);
        }
    };
    if (t == 0) { issue_pair(0); issue_pair(1); issue_pair(2); }

    // ---------------- prologue: wa = W @ a  (2 threads per f) ----------------
    {
        const int f  = t >> 1, hf = t & 1;
        const float* wr = W + (size_t)f * DDIM + hf * 64;
        const float* as = a_s + hf * 64;
        const float* an = a_n + hf * 64;
        float vs = 0.f, vn = 0.f;
#pragma unroll
        for (int j = 0; j < 64; j++) {
            float w = wr[j];
            vs = fmaf(w, as[j], vs);
            vn = fmaf(w, an[j], vn);
        }
        vs += __shfl_xor_sync(0xffffffffu, vs, 1);
        vn += __shfl_xor_sync(0xffffffffu, vn, 1);
        if (!hf) { wa_s_sm[f] = vs; wa_n_sm[f] = vn; }
    }

    // W register cache, packed f32x2 along f.
    const int h = lane >> 4;
    const int d = warp * 16 + (lane & 15);
    ull Wreg2[32];
#pragma unroll
    for (int i = 0; i < 32; i++) {
        int f = h * 64 + 2 * i;
        unsigned lo = __float_as_uint(W[(size_t)f * DDIM + d]);
        unsigned hi = __float_as_uint(W[(size_t)(f + 1) * DDIM + d]);
        Wreg2[i] = ((ull)hi << 32) | lo;
    }
    __syncthreads();

    const float4 wanL = reinterpret_cast<const float4*>(wa_n_sm)[lane];
    const float4 wasL = reinterpret_cast<const float4*>(wa_s_sm)[lane];

    // ---------------- main loop: 4 rows (2 pairs) per iteration ----------------
    int rowA = blockIdx.x;
    int p = 0;
    const int rsel = warp >> 2;        // row within pair
    const int w4   = warp & 3;

    while (rowA < BH) {
        const bool rv1 = rowA + G     < BH;
        const bool rv2 = rowA + 2 * G < BH;
        const bool rv3 = rowA + 3 * G < BH;

        mbar_wait(mbar_base + 8 * (p % NPAIR), (unsigned)((p / NPAIR) & 1));
        if (rv2)
            mbar_wait(mbar_base + 8 * ((p + 1) % NPAIR),
                      (unsigned)(((p + 1) / NPAIR) & 1));

        const float* slotU = &xs[2 * (p % NPAIR) + rsel][0];
        const float* slotV = &xs[2 * ((p + 1) % NPAIR) + rsel][0];
        const int  u  = rsel,  v = rsel + 2;
        const bool wu = (rsel == 0) || rv1;
        const bool wv = rv2 && ((rsel == 0) || rv3);

        // ---- scores: 7 dots per row per warp, two rows interleaved ----
#pragma unroll
        for (int j = 0; j < 7; j++) {
            const int k = w4 + 4 * j;
            if (k <= 26) {
                const int   roff = ((k == 26) ? 0 : k) * FDIM;
                const float4 wv4 = (k == 26) ? wasL : wanL;
                float a = 0.f, b = 0.f;
                if (wu) {
                    float4 x4 = reinterpret_cast<const float4*>(slotU + roff)[lane];
                    a =      x4.x * wv4.x;  a = fmaf(x4.y, wv4.y, a);
                    a = fmaf(x4.z, wv4.z, a); a = fmaf(x4.w, wv4.w, a);
                }
                if (wv) {
                    float4 x4 = reinterpret_cast<const float4*>(slotV + roff)[lane];
                    b =      x4.x * wv4.x;  b = fmaf(x4.y, wv4.y, b);
                    b = fmaf(x4.z, wv4.z, b); b = fmaf(x4.w, wv4.w, b);
                }
#pragma unroll
                for (int o = 16; o; o >>= 1) {
                    a += __shfl_xor_sync(0xffffffffu, a, o);
                    b += __shfl_xor_sync(0xffffffffu, b, o);
                }
                if (lane == 0) {
                    if (wu) sc[u][k] = a;
                    if (wv) sc[v][k] = b;
                }
            }
        }
        __syncthreads();               // B2: scores visible

        // ---- softmax for both rows (no max pass; fp32 exp range is safe) ----
        float pu, pv;
        {
            float va = (lane < 27) ? sc[u][lane] : 0.f;
            float vb = (lane < 27) ? sc[v][lane] : 0.f;
            float sa = __shfl_sync(0xffffffffu, va, 26);
            float sb = __shfl_sync(0xffffffffu, vb, 26);
            float ua = sa + va, ub = sb + vb;
            ua = (ua > 0.f) ? ua : 0.2f * ua;      // LeakyReLU(0.2)
            ub = (ub > 0.f) ? ub : 0.2f * ub;
            float ea = (lane < NK) ? __expf(ua) : 0.f;
            float eb = (lane < NK) ? __expf(ub) : 0.f;
            float za = ea, zb = eb;
#pragma unroll
            for (int o = 16; o; o >>= 1) {
                za += __shfl_xor_sync(0xffffffffu, za, o);
                zb += __shfl_xor_sync(0xffffffffu, zb, o);
            }
            pu = __fdividef(ea, za);
            pv = __fdividef(eb, zb);
        }

        // ---- aggregation (re-read tile rows), both rows interleaved ----
        {
            float4 pa = make_float4(0.f, 0.f, 0.f, 0.f);
            float4 pb = make_float4(0.f, 0.f, 0.f, 0.f);
#pragma unroll
            for (int j = 0; j < 7; j++) {
                const int k = w4 + 4 * j;
                if (k < NK) {
                    float pk = __shfl_sync(0xffffffffu, pu, k);
                    float qk = __shfl_sync(0xffffffffu, pv, k);
                    if (wu) {
                        float4 x4 = reinterpret_cast<const float4*>(slotU + k * FDIM)[lane];
                        pa.x = fmaf(pk, x4.x, pa.x); pa.y = fmaf(pk, x4.y, pa.y);
                        pa.z = fmaf(pk, x4.z, pa.z); pa.w = fmaf(pk, x4.w, pa.w);
                    }
                    if (wv) {
                        float4 x4 = reinterpret_cast<const float4*>(slotV + k * FDIM)[lane];
                        pb.x = fmaf(qk, x4.x, pb.x); pb.y = fmaf(qk, x4.y, pb.y);
                        pb.z = fmaf(qk, x4.z, pb.z); pb.w = fmaf(qk, x4.w, pb.w);
                    }
                }
            }
            if (wu) reinterpret_cast<float4*>(&xpart[u][w4][0])[lane] = pa;
            if (wv) reinterpret_cast<float4*>(&xpart[v][w4][0])[lane] = pb;
        }
        __syncthreads();               // B3: partials visible; tiles dead

        // refill the two consumed pairs
        if (t == 0) { issue_pair(p + 3); issue_pair(p + 4); }

        // ---- reduce 4 partials -> interleaved xagg (f32x2 pairs) ----
        {
            const int r  = t >> 6;     // row 0..3
            const int fp = t & 63;     // f-pair index
            ull q0 = *reinterpret_cast<const ull*>(&xpart[r][0][2 * fp]);
            ull q1 = *reinterpret_cast<const ull*>(&xpart[r][1][2 * fp]);
            ull q2 = *reinterpret_cast<const ull*>(&xpart[r][2][2 * fp]);
            ull q3 = *reinterpret_cast<const ull*>(&xpart[r][3][2 * fp]);
            asm volatile("add.rn.f32x2 %0, %0, %1;\n" : "+l"(q0) : "l"(q1));
            asm volatile("add.rn.f32x2 %0, %0, %1;\n" : "+l"(q2) : "l"(q3));
            asm volatile("add.rn.f32x2 %0, %0, %1;\n" : "+l"(q0) : "l"(q2));
            const int sOff = (fp < 32) ? (8 * (fp >> 1) + 2 * (fp & 1))
                                       : (8 * ((fp - 32) >> 1) + 4 + 2 * (fp & 1));
            *reinterpret_cast<ull*>(&xagg_il[r][sOff]) = q0;
        }
        __syncthreads();               // B4: xagg visible

        // ---- GEMV (4 rows) from packed register W; conflict-free LDS.128 ----
#pragma unroll
        for (int r = 0; r < 4; r++) {
            const bool rok = (r == 0) || (r == 1 && rv1) || (r == 2 && rv2) || (r == 3 && rv3);
            if (rok) {
                ull a0 = 0, a1 = 0;
#pragma unroll
                for (int i = 0; i < 16; i++) {
                    longlong2 q = *reinterpret_cast<const longlong2*>(
                        &xagg_il[r][8 * i + 4 * h]);
                    asm volatile("fma.rn.f32x2 %0, %1, %2, %0;\n"
                                 : "+l"(a0) : "l"((ull)q.x), "l"(Wreg2[2 * i]));
                    asm volatile("fma.rn.f32x2 %0, %1, %2, %0;\n"
                                 : "+l"(a1) : "l"((ull)q.y), "l"(Wreg2[2 * i + 1]));
                }
                float o = __uint_as_float((unsigned)a0) +
                          __uint_as_float((unsigned)(a0 >> 32)) +
                          __uint_as_float((unsigned)a1) +
                          __uint_as_float((unsigned)(a1 >> 32));
                o += __shfl_xor_sync(0xffffffffu, o, 16);   // combine f-halves
                if (h == 0) {
                    int orow = rowA + r * G;
                    out[(size_t)orow * DDIM + d] = (o > 0.f) ? o : 0.f;
                }
            }
        }

        rowA += 4 * G;
        p += 2;
    }
}

// ---------------------------------------------------------------------------
extern "C" void kernel_launch(void* const* d_in, const int* in_sizes, int n_in,
                              void* d_out, int out_size) {
    const float* x_self  = (const float*)d_in[0];   // [1024,32,128]
    const float* x_neigh = (const float*)d_in[1];   // [1024,32,25,128]
    const float* w_feat  = (const float*)d_in[2];   // [128,128]
    const float* a_self  = (const float*)d_in[3];   // [128,1]
    const float* a_neigh = (const float*)d_in[4];   // [128,1]
    float*       out     = (float*)d_out;           // [1024,32,128]

    fused_gat_kernel<<<GRIDSZ, THREADS>>>(x_self, x_neigh, w_feat,
                                          a_self, a_neigh, out);
}

// round 10
// speedup vs baseline: 1.1894x; 1.0151x over previous
#include <cuda_runtime.h>
#include <cstdint>
#include <math.h>

// Problem constants: B=1024, H=32, N=25, F=D=128
#define BH      32768
#define NK      26                  // softmax/aggregation length (self + 25)
#define FDIM    128
#define DDIM    128
#define GRIDSZ  304                 // 2 blocks/SM x 152 SMs (GB300)
#define THREADS 256
#define NPAIR   3                   // TMA ring depth in row-pairs
#define NSLOT   (2 * NPAIR)

#define ROW_FLOATS   (NK * FDIM)    // 3328 floats per staged row tile
#define SELF_BYTES   (FDIM * 4)     // 512
#define NEIGH_BYTES  (25 * FDIM * 4)// 12800
#define ROW_BYTES    (SELF_BYTES + NEIGH_BYTES) // 13312

typedef unsigned long long ull;

// ---------------------------------------------------------------------------
// TMA 1D bulk copy + mbarrier helpers
// ---------------------------------------------------------------------------
__device__ __forceinline__ void tma_bulk_1d(unsigned dst, const void* src,
                                            unsigned bytes, unsigned mbar) {
    asm volatile(
        "cp.async.bulk.shared::cluster.global.mbarrier::complete_tx::bytes "
        "[%0], [%1], %2, [%3];\n"
        :: "r"(dst), "l"(src), "r"(bytes), "r"(mbar) : "memory");
}
__device__ __forceinline__ void mbar_init(unsigned mbar, unsigned cnt) {
    asm volatile("mbarrier.init.shared.b64 [%0], %1;\n" :: "r"(mbar), "r"(cnt) : "memory");
}
__device__ __forceinline__ void mbar_expect_tx(unsigned mbar, unsigned bytes) {
    asm volatile("mbarrier.arrive.expect_tx.shared.b64 _, [%0], %1;\n"
                 :: "r"(mbar), "r"(bytes) : "memory");
}
__device__ __forceinline__ void mbar_wait(unsigned mbar, unsigned parity) {
    asm volatile(
        "{\n\t"
        ".reg .pred P;\n\t"
        "WL_%=:\n\t"
        "mbarrier.try_wait.parity.acquire.cta.shared::cta.b64 P, [%0], %1, 0x989680;\n\t"
        "@P bra WD_%=;\n\t"
        "bra WL_%=;\n\t"
        "WD_%=:\n\t"
        "}"
        :: "r"(mbar), "r"(parity) : "memory");
}

__global__ void __launch_bounds__(THREADS, 2)
fused_gat_kernel(const float* __restrict__ x_self,
                 const float* __restrict__ x_neigh,
                 const float* __restrict__ W,
                 const float* __restrict__ a_s,
                 const float* __restrict__ a_n,
                 float* __restrict__ out) {
    __shared__ __align__(128) float xs[NSLOT][ROW_FLOATS];      // ~80 KB ring
    __shared__ __align__(16)  float wa_s_sm[FDIM];
    __shared__ __align__(16)  float wa_n_sm[FDIM];
    __shared__ __align__(16)  float xpart[4][4][FDIM];           // per-warp e-weighted partials
    __shared__ float zpart[4][4];                                // per-warp exp sums
    __shared__ __align__(16)  float xagg_il[4][FDIM];            // interleaved for GEMV
    __shared__ __align__(8)   ull  mbars[NPAIR];

    const int t    = threadIdx.x;
    const int warp = t >> 5;
    const int lane = t & 31;

    const unsigned xs_base   = (unsigned)__cvta_generic_to_shared(&xs[0][0]);
    const unsigned mbar_base = (unsigned)__cvta_generic_to_shared(&mbars[0]);

    if (t == 0) {
#pragma unroll
        for (int i = 0; i < NPAIR; i++) mbar_init(mbar_base + 8 * i, 1);
        asm volatile("fence.proxy.async.shared::cta;\n" ::: "memory");
    }
    __syncthreads();

    const int G = GRIDSZ;
    auto issue_pair = [&](int p) {
        int rA = blockIdx.x + 2 * p * G;
        if (rA >= BH) return;
        int rB = rA + G;
        int nrows = (rB < BH) ? 2 : 1;
        unsigned mb = mbar_base + 8 * (p % NPAIR);
        unsigned s0 = xs_base + (unsigned)(2 * (p % NPAIR)) * (ROW_FLOATS * 4);
        mbar_expect_tx(mb, (unsigned)ROW_BYTES * nrows);
        tma_bulk_1d(s0,              x_self  + (size_t)rA * FDIM,      SELF_BYTES,  mb);
        tma_bulk_1d(s0 + SELF_BYTES, x_neigh + (size_t)rA * 25 * FDIM, NEIGH_BYTES, mb);
        if (nrows == 2) {
            unsigned s1 = s0 + ROW_FLOATS * 4;
            tma_bulk_1d(s1,              x_self  + (size_t)rB * FDIM,      SELF_BYTES,  mb);
            tma_bulk_1d(s1 + SELF_BYTES, x_neigh + (size_t)rB * 25 * FDIM, NEIGH_BYTES, mb);
        }
    };
    if (t == 0) { issue_pair(0); issue_pair(1); issue_pair(2); }

    // ---------------- prologue: wa = W @ a  (2 threads per f) ----------------
    {
        const int f  = t >> 1, hf = t & 1;
        const float* wr = W + (size_t)f * DDIM + hf * 64;
        const float* as = a_s + hf * 64;
        const float* an = a_n + hf * 64;
        float vs = 0.f, vn = 0.f;
#pragma unroll
        for (int j = 0; j < 64; j++) {
            float w = wr[j];
            vs = fmaf(w, as[j], vs);
            vn = fmaf(w, an[j], vn);
        }
        vs += __shfl_xor_sync(0xffffffffu, vs, 1);
        vn += __shfl_xor_sync(0xffffffffu, vn, 1);
        if (!hf) { wa_s_sm[f] = vs; wa_n_sm[f] = vn; }
    }

    // W register cache, packed f32x2 along f.
    const int h = lane >> 4;
    const int d = warp * 16 + (lane & 15);
    ull Wreg2[32];
#pragma unroll
    for (int i = 0; i < 32; i++) {
        int f = h * 64 + 2 * i;
        unsigned lo = __float_as_uint(W[(size_t)f * DDIM + d]);
        unsigned hi = __float_as_uint(W[(size_t)(f + 1) * DDIM + d]);
        Wreg2[i] = ((ull)hi << 32) | lo;
    }
    __syncthreads();

    const float4 wanL = reinterpret_cast<const float4*>(wa_n_sm)[lane];
    const float4 wasL = reinterpret_cast<const float4*>(wa_s_sm)[lane];

    // warp-reduce-to-all helper
#define WREDUCE(x)                                                     \
    do {                                                               \
        x += __shfl_xor_sync(0xffffffffu, x, 16);                      \
        x += __shfl_xor_sync(0xffffffffu, x, 8);                       \
        x += __shfl_xor_sync(0xffffffffu, x, 4);                       \
        x += __shfl_xor_sync(0xffffffffu, x, 2);                       \
        x += __shfl_xor_sync(0xffffffffu, x, 1);                       \
    } while (0)

    // ---------------- main loop: 4 rows (2 pairs) per iteration ----------------
    int rowA = blockIdx.x;
    int p = 0;
    const int rsel = warp >> 2;        // row within pair
    const int w4   = warp & 3;

    while (rowA < BH) {
        const bool rv1 = rowA + G     < BH;
        const bool rv2 = rowA + 2 * G < BH;
        const bool rv3 = rowA + 3 * G < BH;

        mbar_wait(mbar_base + 8 * (p % NPAIR), (unsigned)((p / NPAIR) & 1));
        if (rv2)
            mbar_wait(mbar_base + 8 * ((p + 1) % NPAIR),
                      (unsigned)(((p + 1) / NPAIR) & 1));

        const float* slotU = &xs[2 * (p % NPAIR) + rsel][0];
        const float* slotV = &xs[2 * ((p + 1) % NPAIR) + rsel][0];
        const int  u  = rsel,  v = rsel + 2;
        const bool wu = (rsel == 0) || rv1;
        const bool wv = rv2 && ((rsel == 0) || rv3);

        // ---- single-pass online softmax + aggregation, 2 rows interleaved ----
        // self-score ss = row0 . wa_s (redundant per warp); for k = w4+4j < 26:
        //   s_k = row_k . wa_n;  e_k = exp(LR(ss + s_k));  part += e_k*x4; z += e_k
        float4 paU = make_float4(0.f, 0.f, 0.f, 0.f);
        float4 paV = make_float4(0.f, 0.f, 0.f, 0.f);
        float  zU = 0.f, zV = 0.f;
        float4 x0U, x0V;
        float  ssU = 0.f, ssV = 0.f;

        if (wu) {
            x0U = reinterpret_cast<const float4*>(slotU)[lane];
            ssU =      x0U.x * wasL.x;  ssU = fmaf(x0U.y, wasL.y, ssU);
            ssU = fmaf(x0U.z, wasL.z, ssU); ssU = fmaf(x0U.w, wasL.w, ssU);
        }
        if (wv) {
            x0V = reinterpret_cast<const float4*>(slotV)[lane];
            ssV =      x0V.x * wasL.x;  ssV = fmaf(x0V.y, wasL.y, ssV);
            ssV = fmaf(x0V.z, wasL.z, ssV); ssV = fmaf(x0V.w, wasL.w, ssV);
        }
        WREDUCE(ssU);
        WREDUCE(ssV);

#pragma unroll
        for (int j = 0; j < 7; j++) {
            const int k = w4 + 4 * j;
            if (k < NK) {
                float4 xU, xV;
                float  aS = 0.f, bS = 0.f;
                if (wu) {
                    xU = (k == 0) ? x0U
                       : reinterpret_cast<const float4*>(slotU + k * FDIM)[lane];
                    aS =      xU.x * wanL.x;  aS = fmaf(xU.y, wanL.y, aS);
                    aS = fmaf(xU.z, wanL.z, aS); aS = fmaf(xU.w, wanL.w, aS);
                }
                if (wv) {
                    xV = (k == 0) ? x0V
                       : reinterpret_cast<const float4*>(slotV + k * FDIM)[lane];
                    bS =      xV.x * wanL.x;  bS = fmaf(xV.y, wanL.y, bS);
                    bS = fmaf(xV.z, wanL.z, bS); bS = fmaf(xV.w, wanL.w, bS);
                }
                WREDUCE(aS);
                WREDUCE(bS);
                if (wu) {
                    float uu = ssU + aS;
                    uu = (uu > 0.f) ? uu : 0.2f * uu;   // LeakyReLU(0.2)
                    float e = __expf(uu);
                    paU.x = fmaf(e, xU.x, paU.x); paU.y = fmaf(e, xU.y, paU.y);
                    paU.z = fmaf(e, xU.z, paU.z); paU.w = fmaf(e, xU.w, paU.w);
                    zU += e;
                }
                if (wv) {
                    float uu = ssV + bS;
                    uu = (uu > 0.f) ? uu : 0.2f * uu;
                    float e = __expf(uu);
                    paV.x = fmaf(e, xV.x, paV.x); paV.y = fmaf(e, xV.y, paV.y);
                    paV.z = fmaf(e, xV.z, paV.z); paV.w = fmaf(e, xV.w, paV.w);
                    zV += e;
                }
            }
        }
        if (wu) {
            reinterpret_cast<float4*>(&xpart[u][w4][0])[lane] = paU;
            if (lane == 0) zpart[u][w4] = zU;
        }
        if (wv) {
            reinterpret_cast<float4*>(&xpart[v][w4][0])[lane] = paV;
            if (lane == 0) zpart[v][w4] = zV;
        }
        __syncthreads();               // B3: partials visible; tiles dead

        // refill the two consumed pairs
        if (t == 0) { issue_pair(p + 3); issue_pair(p + 4); }

        // ---- reduce 4 partials, divide by Z -> interleaved xagg ----
        {
            const int r  = t >> 6;     // row 0..3
            const int fp = t & 63;     // f-pair index
            ull q0 = *reinterpret_cast<const ull*>(&xpart[r][0][2 * fp]);
            ull q1 = *reinterpret_cast<const ull*>(&xpart[r][1][2 * fp]);
            ull q2 = *reinterpret_cast<const ull*>(&xpart[r][2][2 * fp]);
            ull q3 = *reinterpret_cast<const ull*>(&xpart[r][3][2 * fp]);
            asm volatile("add.rn.f32x2 %0, %0, %1;\n" : "+l"(q0) : "l"(q1));
            asm volatile("add.rn.f32x2 %0, %0, %1;\n" : "+l"(q2) : "l"(q3));
            asm volatile("add.rn.f32x2 %0, %0, %1;\n" : "+l"(q0) : "l"(q2));
            float rz = __fdividef(1.f, zpart[r][0] + zpart[r][1]
                                     + zpart[r][2] + zpart[r][3]);
            ull rz2;
            asm volatile("mov.b64 %0, {%1, %1};\n" : "=l"(rz2) : "f"(rz));
            asm volatile("mul.rn.f32x2 %0, %0, %1;\n" : "+l"(q0) : "l"(rz2));
            const int sOff = (fp < 32) ? (8 * (fp >> 1) + 2 * (fp & 1))
                                       : (8 * ((fp - 32) >> 1) + 4 + 2 * (fp & 1));
            *reinterpret_cast<ull*>(&xagg_il[r][sOff]) = q0;
        }
        __syncthreads();               // B4: xagg visible

        // ---- GEMV (4 rows) from packed register W; conflict-free LDS.128 ----
#pragma unroll
        for (int r = 0; r < 4; r++) {
            const bool rok = (r == 0) || (r == 1 && rv1) || (r == 2 && rv2) || (r == 3 && rv3);
            if (rok) {
                ull a0 = 0, a1 = 0;
#pragma unroll
                for (int i = 0; i < 16; i++) {
                    longlong2 q = *reinterpret_cast<const longlong2*>(
                        &xagg_il[r][8 * i + 4 * h]);
                    asm volatile("fma.rn.f32x2 %0, %1, %2, %0;\n"
                                 : "+l"(a0) : "l"((ull)q.x), "l"(Wreg2[2 * i]));
                    asm volatile("fma.rn.f32x2 %0, %1, %2, %0;\n"
                                 : "+l"(a1) : "l"((ull)q.y), "l"(Wreg2[2 * i + 1]));
                }
                float o = __uint_as_float((unsigned)a0) +
                          __uint_as_float((unsigned)(a0 >> 32)) +
                          __uint_as_float((unsigned)a1) +
                          __uint_as_float((unsigned)(a1 >> 32));
                o += __shfl_xor_sync(0xffffffffu, o, 16);   // combine f-halves
                if (h == 0) {
                    int orow = rowA + r * G;
                    out[(size_t)orow * DDIM + d] = (o > 0.f) ? o : 0.f;
                }
            }
        }

        rowA += 4 * G;
        p += 2;
    }
#undef WREDUCE
}

// ---------------------------------------------------------------------------
extern "C" void kernel_launch(void* const* d_in, const int* in_sizes, int n_in,
                              void* d_out, int out_size) {
    const float* x_self  = (const float*)d_in[0];   // [1024,32,128]
    const float* x_neigh = (const float*)d_in[1];   // [1024,32,25,128]
    const float* w_feat  = (const float*)d_in[2];   // [128,128]
    const float* a_self  = (const float*)d_in[3];   // [128,1]
    const float* a_neigh = (const float*)d_in[4];   // [128,1]
    float*       out     = (float*)d_out;           // [1024,32,128]

    fused_gat_kernel<<<GRIDSZ, THREADS>>>(x_self, x_neigh, w_feat,
                                          a_self, a_neigh, out);
}